// round 6
// baseline (speedup 1.0000x reference)
#include <cuda_runtime.h>
#include <cstdint>
#include <cstddef>

#define Bx 128
#define Hx 1024
#define Fx 138
#define Tx 1024
#define NCTA 128

// ---- persistent scratch (__device__ globals = sanctioned path) ----
__device__ float g_W1p[4096L * 1184];   // packed tf32 [Whh1 | Wih1(pad->1184)]
__device__ float g_W2p[4096L * 2048];   // packed tf32 [Wih2 | Whh2]
__device__ float g_Wh1p[128L * 1024];   // head W1 tf32
__device__ float g_Wh2p[128L * 128];    // head W2 tf32
__device__ float g_bs1[4096], g_bs2[4096];
__device__ float g_xp[(size_t)Tx * Bx * 160];     // x padded to stride 160
__device__ float g_h1[2][Bx * Hx];
__device__ float g_c1[Bx * Hx], g_c2[Bx * Hx], g_hz[Bx * Hx];
__device__ float g_h2all[(size_t)Tx * Bx * Hx];   // all h2_t (head input)
__device__ float g_hid[(size_t)Tx * Bx * 128];    // selu(hidden)
__device__ unsigned g_cnt, g_gen;

// ---- helpers ----
__device__ __forceinline__ float tf32r(float x) {
    uint32_t u; asm("cvt.rna.tf32.f32 %0, %1;" : "=r"(u) : "f"(x));
    return __uint_as_float(u);
}
__device__ __forceinline__ float sigm(float x) { return 1.f / (1.f + __expf(-x)); }
__device__ __forceinline__ void cp16(float* d, const float* s) {
    uint32_t a = (uint32_t)__cvta_generic_to_shared(d);
    asm volatile("cp.async.ca.shared.global [%0], [%1], 16;" :: "r"(a), "l"(s));
}

struct SMt {
    float As[2][128 * 36];
    float Bs[2][32 * 36];
    float bb[32];
};

__device__ __forceinline__ void gridsync() {
    __syncthreads();
    if (threadIdx.x == 0) {
        __threadfence();
        volatile unsigned* genp = &g_gen;
        unsigned gen = *genp;
        if (atomicAdd(&g_cnt, 1u) == NCTA - 1) {
            g_cnt = 0;
            __threadfence();
            *genp = gen + 1;
        } else {
            while (*genp == gen) __nanosleep(64);
        }
        __threadfence();
    }
    __syncthreads();
}

__global__ void initz() {
    for (int i = blockIdx.x * blockDim.x + threadIdx.x; i < Bx * Hx;
         i += gridDim.x * blockDim.x) {
        g_h1[0][i] = 0.f; g_h1[1][i] = 0.f;
        g_c1[i] = 0.f; g_c2[i] = 0.f; g_hz[i] = 0.f;
    }
}

// ---- prepack: gate-interleave (32-col groups) + tf32 RNE + x padding ----
// packed row p: cta=p>>5, gate=(p>>3)&3, u=p&7 -> orig r = gate*1024 + (p>>5)*8 + (p&7)
__global__ void prepack(const float* __restrict__ x,
                        const float* __restrict__ Wih1, const float* __restrict__ bih1,
                        const float* __restrict__ Whh1, const float* __restrict__ bhh1,
                        const float* __restrict__ Wih2, const float* __restrict__ bih2,
                        const float* __restrict__ Whh2, const float* __restrict__ bhh2,
                        const float* __restrict__ W1, const float* __restrict__ W2) {
    long t0 = blockIdx.x * (long)blockDim.x + threadIdx.x;
    long st = (long)gridDim.x * blockDim.x;
    for (long i = t0; i < 4096L * 2048; i += st) {
        int p = (int)(i >> 11), k = (int)(i & 2047);
        int r = ((p >> 3) & 3) * 1024 + (p >> 5) * 8 + (p & 7);
        g_W2p[i] = tf32r(k < 1024 ? Wih2[(long)r * 1024 + k]
                                  : Whh2[(long)r * 1024 + k - 1024]);
    }
    for (long i = t0; i < 4096L * 1184; i += st) {
        int p = (int)(i / 1184), k = (int)(i % 1184);
        int r = ((p >> 3) & 3) * 1024 + (p >> 5) * 8 + (p & 7);
        float v = 0.f;
        if (k < 1024) v = Whh1[(long)r * 1024 + k];
        else if (k < 1024 + Fx) v = Wih1[(long)r * Fx + k - 1024];
        g_W1p[i] = tf32r(v);
    }
    for (long i = t0; i < (long)Tx * Bx * 160; i += st) {
        long rb = i / 160; int k = (int)(i % 160);
        g_xp[i] = (k < Fx) ? x[rb * Fx + k] : 0.f;
    }
    for (long i = t0; i < 128L * 1024; i += st) g_Wh1p[i] = tf32r(W1[i]);
    for (long i = t0; i < 128L * 128;  i += st) g_Wh2p[i] = tf32r(W2[i]);
    for (long i = t0; i < 4096; i += st) {
        int p = (int)i;
        int r = ((p >> 3) & 3) * 1024 + (p >> 5) * 8 + (p & 7);
        g_bs1[p] = bih1[r] + bhh1[r];
        g_bs2[p] = bih2[r] + bhh2[r];
    }
}

// ---- GEMM core: C[128 x 32cols@cta] = A[128 x KP] @ Wp^T (+epilogue) ----
// A = [A0 (c0 cols, stride s0) | A1 (c1 cols, stride s1)], KP = c0 + c1 (A1 may be pad)
// MODE 0: LSTM cell; MODE 1: selu->out[.,128]; MODE 2: plain->out[.,128]
template <int MODE>
__device__ __forceinline__ void gemm(
    const float* __restrict__ A0, long s0, int c0,
    const float* __restrict__ A1, long s1, int c1,
    const float* __restrict__ W, int KP,
    const float* __restrict__ bias,
    float* cst, float* out, int cta, int row0, SMt& sm) {
    const int tid = threadIdx.x;
    const int w = tid >> 5, l = tid & 31, g = l >> 2, q = l & 3;
    const int nch = KP >> 5;
    const bool a1fast = ((s1 & 3) == 0) && A1 != nullptr;

    if (tid < 32) sm.bb[tid] = bias[cta * 32 + tid];

    float acc[4][4];
#pragma unroll
    for (int a = 0; a < 4; a++)
#pragma unroll
        for (int j = 0; j < 4; j++) acc[a][j] = 0.f;

    auto stage = [&](int ch) {
        int k0 = ch << 5;
        float* Ab = sm.As[ch & 1];
        float* Bb = sm.Bs[ch & 1];
        if (k0 + 32 <= c0) {
#pragma unroll
            for (int i = tid; i < 1024; i += 256) {
                int r = i >> 3, qq = i & 7;
                cp16(Ab + r * 36 + qq * 4, A0 + (row0 + r) * s0 + k0 + qq * 4);
            }
        } else if (k0 >= c0 && a1fast) {
#pragma unroll
            for (int i = tid; i < 1024; i += 256) {
                int r = i >> 3, qq = i & 7;
                cp16(Ab + r * 36 + qq * 4, A1 + (row0 + r) * s1 + (k0 - c0) + qq * 4);
            }
        } else {
            for (int i = tid; i < 4096; i += 256) {
                int r = i >> 5, kk = i & 31, k = k0 + kk;
                float v = 0.f;
                if (k < c0) v = A0[(row0 + r) * s0 + k];
                else if (k - c0 < c1) v = A1[(row0 + r) * s1 + k - c0];
                Ab[r * 36 + kk] = v;
            }
        }
        const float* Wb = W + (size_t)cta * 32 * KP + k0;
        {
            int c = tid >> 3, qq = tid & 7;
            cp16(Bb + c * 36 + qq * 4, Wb + (size_t)c * KP + qq * 4);
        }
        asm volatile("cp.async.commit_group;");
    };

    stage(0);
    for (int ch = 0; ch < nch; ch++) {
        if (ch + 1 < nch) { stage(ch + 1); asm volatile("cp.async.wait_group 1;"); }
        else              { asm volatile("cp.async.wait_group 0;"); }
        __syncthreads();
        const float* Ab = sm.As[ch & 1];
        const float* Bb = sm.Bs[ch & 1];
#pragma unroll
        for (int kf = 0; kf < 4; kf++) {
            int kb = kf << 3;
            float a0 = tf32r(Ab[(16 * w + g) * 36 + kb + q]);
            float a1 = tf32r(Ab[(16 * w + g + 8) * 36 + kb + q]);
            float a2 = tf32r(Ab[(16 * w + g) * 36 + kb + q + 4]);
            float a3 = tf32r(Ab[(16 * w + g + 8) * 36 + kb + q + 4]);
#pragma unroll
            for (int nf = 0; nf < 4; nf++) {
                float b0 = Bb[(8 * nf + g) * 36 + kb + q];
                float b1 = Bb[(8 * nf + g) * 36 + kb + q + 4];
                asm volatile(
                    "mma.sync.aligned.m16n8k8.row.col.f32.tf32.tf32.f32 "
                    "{%0,%1,%2,%3},{%4,%5,%6,%7},{%8,%9},{%0,%1,%2,%3};"
                    : "+f"(acc[nf][0]), "+f"(acc[nf][1]), "+f"(acc[nf][2]), "+f"(acc[nf][3])
                    : "r"(__float_as_uint(a0)), "r"(__float_as_uint(a1)),
                      "r"(__float_as_uint(a2)), "r"(__float_as_uint(a3)),
                      "r"(__float_as_uint(b0)), "r"(__float_as_uint(b1)));
            }
        }
        __syncthreads();
    }

#pragma unroll
    for (int nf = 0; nf < 4; nf++)
#pragma unroll
        for (int j = 0; j < 4; j++) acc[nf][j] += sm.bb[8 * nf + 2 * q + (j & 1)];

    if (MODE == 0) {
#pragma unroll
        for (int j = 0; j < 4; j++) {
            int m = 16 * w + g + 8 * (j >> 1);
            int u = 2 * q + (j & 1);
            float iv = sigm(acc[0][j]);
            float fv = sigm(acc[1][j]);
            float gv = tanhf(acc[2][j]);
            float ov = sigm(acc[3][j]);
            long idx = (long)m * Hx + cta * 8 + u;
            float cn = fv * cst[idx] + iv * gv;
            cst[idx] = cn;
            out[idx] = ov * tanhf(cn);
        }
    } else {
#pragma unroll
        for (int nf = 0; nf < 4; nf++)
#pragma unroll
            for (int j = 0; j < 4; j++) {
                int m = 16 * w + g + 8 * (j >> 1);
                int col = cta * 32 + 8 * nf + 2 * q + (j & 1);
                float v = acc[nf][j];
                if (MODE == 1)
                    v = v > 0.f ? 1.0507009873554805f * v
                                : 1.7580993408473766f * (__expf(v) - 1.f);
                out[(size_t)(row0 + m) * 128 + col] = v;
            }
    }
}

// ---- persistent recurrence: 128 CTAs, grid barrier between layers/steps ----
__global__ void __launch_bounds__(256, 1) persist() {
    __shared__ SMt sm;
    const int cta = blockIdx.x;
    for (int t = 0; t < Tx; t++) {
        const float* h1r = g_h1[(t + 1) & 1];
        float*       h1w = g_h1[t & 1];
        const float* h2r = (t == 0) ? g_hz : g_h2all + (size_t)(t - 1) * Bx * Hx;
        float*       h2w = g_h2all + (size_t)t * Bx * Hx;
        const float* xt  = g_xp + (size_t)t * Bx * 160;
        gemm<0>(h1r, 1024, 1024, xt, 160, 160, g_W1p, 1184, g_bs1, g_c1, h1w, cta, 0, sm);
        gridsync();
        gemm<0>(h1w, 1024, 1024, h2r, 1024, 1024, g_W2p, 2048, g_bs2, g_c2, h2w, cta, 0, sm);
        gridsync();
    }
}

// ---- batched MLP head over all T*B rows ----
__global__ void __launch_bounds__(256) headk(int mode, const float* __restrict__ A,
                                             long sA, int cA,
                                             const float* __restrict__ W, int KP,
                                             const float* __restrict__ bias,
                                             float* out) {
    __shared__ SMt sm;
    if (mode == 1)
        gemm<1>(A, sA, cA, nullptr, 0, 0, W, KP, bias, nullptr, out,
                blockIdx.x, blockIdx.y * 128, sm);
    else
        gemm<2>(A, sA, cA, nullptr, 0, 0, W, KP, bias, nullptr, out,
                blockIdx.x, blockIdx.y * 128, sm);
}

extern "C" void kernel_launch(void* const* d_in, const int* in_sizes, int n_in,
                              void* d_out, int out_size) {
    const float* x    = (const float*)d_in[0];
    const float* Wih1 = (const float*)d_in[1]; const float* bih1 = (const float*)d_in[2];
    const float* Whh1 = (const float*)d_in[3]; const float* bhh1 = (const float*)d_in[4];
    const float* Wih2 = (const float*)d_in[5]; const float* bih2 = (const float*)d_in[6];
    const float* Whh2 = (const float*)d_in[7]; const float* bhh2 = (const float*)d_in[8];
    const float* W1   = (const float*)d_in[9]; const float* b1   = (const float*)d_in[10];
    const float* W2   = (const float*)d_in[11]; const float* b2  = (const float*)d_in[12];

    float *Wh1p, *Wh2p, *h2all, *hid;
    cudaGetSymbolAddress((void**)&Wh1p,  g_Wh1p);
    cudaGetSymbolAddress((void**)&Wh2p,  g_Wh2p);
    cudaGetSymbolAddress((void**)&h2all, g_h2all);
    cudaGetSymbolAddress((void**)&hid,   g_hid);

    initz<<<128, 256>>>();
    prepack<<<1024, 256>>>(x, Wih1, bih1, Whh1, bhh1, Wih2, bih2, Whh2, bhh2, W1, W2);
    persist<<<NCTA, 256>>>();
    headk<<<dim3(4, 1024), 256>>>(1, h2all, 1024, 1024, Wh1p, 1024, b1, hid);
    headk<<<dim3(4, 1024), 256>>>(2, hid, 128, 128, Wh2p, 128, b2, (float*)d_out);
}

// round 9
// speedup vs baseline: 1.0769x; 1.0769x over previous
#include <cuda_runtime.h>
#include <cstdint>
#include <cstddef>

#define Bx 128
#define Hx 1024
#define Fx 138
#define Tx 1024
#define NCTA 128
#define KP1 1184
#define KP2 2048
#define XPAD 160
#define NCH1 37
#define NCH2 64

// ---- persistent scratch ----
__device__ float g_W1p[4096L * KP1];
__device__ float g_W2p[4096L * KP2];
__device__ float g_Wh1p[128L * 1024];
__device__ float g_Wh2p[128L * 128];
__device__ float g_bs1[4096], g_bs2[4096];
__device__ float g_xp[(size_t)Tx * Bx * XPAD];
__device__ float g_h1[2][Bx * Hx];
__device__ float g_hz[Bx * Hx];
__device__ float g_h2all[(size_t)Tx * Bx * Hx];
__device__ float g_hid[(size_t)Tx * Bx * 128];
__device__ unsigned g_cnt, g_gen;

// ---- helpers ----
__device__ __forceinline__ float tf32r(float x) {
    uint32_t u; asm("cvt.rna.tf32.f32 %0, %1;" : "=r"(u) : "f"(x));
    return __uint_as_float(u);
}
__device__ __forceinline__ float sigm(float x) { return 1.f / (1.f + __expf(-x)); }
__device__ __forceinline__ void cp16g(float* d, const float* s) {
    uint32_t a = (uint32_t)__cvta_generic_to_shared(d);
    asm volatile("cp.async.ca.shared.global [%0], [%1], 16;" :: "r"(a), "l"(s));
}
__device__ __forceinline__ void mma8(float* c, float a0, float a1, float a2, float a3,
                                     float b0, float b1) {
    asm volatile(
        "mma.sync.aligned.m16n8k8.row.col.f32.tf32.tf32.f32 "
        "{%0,%1,%2,%3},{%4,%5,%6,%7},{%8,%9},{%0,%1,%2,%3};"
        : "+f"(c[0]), "+f"(c[1]), "+f"(c[2]), "+f"(c[3])
        : "r"(__float_as_uint(a0)), "r"(__float_as_uint(a1)),
          "r"(__float_as_uint(a2)), "r"(__float_as_uint(a3)),
          "r"(__float_as_uint(b0)), "r"(__float_as_uint(b1)));
}

__device__ __forceinline__ void gridsync() {
    __syncthreads();
    if (threadIdx.x == 0) {
        __threadfence();
        volatile unsigned* genp = &g_gen;
        unsigned gen = *genp;
        if (atomicAdd(&g_cnt, 1u) == NCTA - 1) {
            g_cnt = 0;
            __threadfence();
            *genp = gen + 1;
        } else {
            while (*genp == gen) __nanosleep(64);
        }
        __threadfence();
    }
    __syncthreads();
}

__global__ void initz() {
    for (int i = blockIdx.x * blockDim.x + threadIdx.x; i < Bx * Hx;
         i += gridDim.x * blockDim.x) {
        g_h1[0][i] = 0.f; g_h1[1][i] = 0.f; g_hz[i] = 0.f;
    }
}

__global__ void dummyk() {}

// ---- prepack: gate-interleave (32-col CTA groups) + tf32 RNE + x pad/round ----
// packed row p: cta=p>>5, gate=(p>>3)&3, u=p&7 -> r = gate*1024 + (p>>5)*8 + (p&7)
__global__ void prepack(const float* __restrict__ x,
                        const float* __restrict__ Wih1, const float* __restrict__ bih1,
                        const float* __restrict__ Whh1, const float* __restrict__ bhh1,
                        const float* __restrict__ Wih2, const float* __restrict__ bih2,
                        const float* __restrict__ Whh2, const float* __restrict__ bhh2,
                        const float* __restrict__ W1, const float* __restrict__ W2) {
    long t0 = blockIdx.x * (long)blockDim.x + threadIdx.x;
    long st = (long)gridDim.x * blockDim.x;
    for (long i = t0; i < 4096L * KP2; i += st) {
        int p = (int)(i >> 11), k = (int)(i & 2047);
        int r = ((p >> 3) & 3) * 1024 + (p >> 5) * 8 + (p & 7);
        g_W2p[i] = tf32r(k < 1024 ? Wih2[(long)r * 1024 + k]
                                  : Whh2[(long)r * 1024 + k - 1024]);
    }
    for (long i = t0; i < 4096L * KP1; i += st) {
        int p = (int)(i / KP1), k = (int)(i % KP1);
        int r = ((p >> 3) & 3) * 1024 + (p >> 5) * 8 + (p & 7);
        float v = 0.f;
        if (k < 1024) v = Whh1[(long)r * 1024 + k];
        else if (k < 1024 + Fx) v = Wih1[(long)r * Fx + k - 1024];
        g_W1p[i] = tf32r(v);
    }
    for (long i = t0; i < (long)Tx * Bx * XPAD; i += st) {
        long rb = i / XPAD; int k = (int)(i % XPAD);
        g_xp[i] = (k < Fx) ? tf32r(x[rb * Fx + k]) : 0.f;
    }
    for (long i = t0; i < 128L * 1024; i += st) g_Wh1p[i] = tf32r(W1[i]);
    for (long i = t0; i < 128L * 128;  i += st) g_Wh2p[i] = tf32r(W2[i]);
    for (long i = t0; i < 4096; i += st) {
        int p = (int)i;
        int r = ((p >> 3) & 3) * 1024 + (p >> 5) * 8 + (p & 7);
        g_bs1[p] = bih1[r] + bhh1[r];
        g_bs2[p] = bih2[r] + bhh2[r];
    }
}

// ---- persistent recurrence: 128 CTAs x 128 thr, warp tile M32xN32 ----
__global__ void __launch_bounds__(128, 1) persist() {
    extern __shared__ float dsm[];
    float* As = dsm;                 // [3][128*36]
    float* Bs = dsm + 3 * 4608;      // [3][32*36]
    float* bb = dsm + 3 * 4608 + 3 * 1152;  // [32]
    const int tid = threadIdx.x, cta = blockIdx.x;
    const int w = tid >> 5, l = tid & 31, g = l >> 2, q = l & 3;

    float c1s[2][4], c2s[2][4];
#pragma unroll
    for (int a = 0; a < 2; a++)
#pragma unroll
        for (int j = 0; j < 4; j++) { c1s[a][j] = 0.f; c2s[a][j] = 0.f; }

    auto run_layer = [&](const float* __restrict__ A0, const float* __restrict__ A1,
                         long s1, const float* __restrict__ W, int KP, int nch,
                         const float* __restrict__ bias, float (*cs)[4],
                         float* __restrict__ hdst) {
        __syncthreads();   // protect bb + smem bufs vs previous layer's readers
        if (tid < 32) bb[tid] = bias[cta * 32 + tid];

        float acc[2][4][4];
#pragma unroll
        for (int mf = 0; mf < 2; mf++)
#pragma unroll
            for (int nf = 0; nf < 4; nf++)
#pragma unroll
                for (int j = 0; j < 4; j++) acc[mf][nf][j] = 0.f;

        auto stage = [&](int c) {
            int j = c % 3, k0 = c << 5;
            float* Ab = As + j * 4608;
            float* Bb = Bs + j * 1152;
            const bool inA0 = (k0 < 1024);
#pragma unroll
            for (int it = 0; it < 8; it++) {
                int i = tid + it * 128;
                int r = i >> 3, q8 = i & 7;
                const float* src = inA0 ? A0 + (size_t)r * 1024 + k0 + q8 * 4
                                        : A1 + (size_t)r * s1 + (k0 - 1024) + q8 * 4;
                cp16g(Ab + r * 36 + q8 * 4, src);
            }
#pragma unroll
            for (int it = 0; it < 2; it++) {
                int i = tid + it * 128;
                int n = i >> 3, q8 = i & 7;
                cp16g(Bb + n * 36 + q8 * 4,
                      W + (size_t)(cta * 32 + n) * KP + k0 + q8 * 4);
            }
            asm volatile("cp.async.commit_group;" ::: "memory");
        };

        stage(0); stage(1);
        for (int c = 0; c < nch; c++) {
            if (c + 1 < nch) asm volatile("cp.async.wait_group 1;" ::: "memory");
            else             asm volatile("cp.async.wait_group 0;" ::: "memory");
            __syncthreads();
            if (c + 2 < nch) stage(c + 2);
            const float* Ab = As + (c % 3) * 4608;
            const float* Bb = Bs + (c % 3) * 1152;
#pragma unroll
            for (int kf = 0; kf < 4; kf++) {
                int kb = kf << 3;
                float bf[4][2];
#pragma unroll
                for (int nf = 0; nf < 4; nf++) {
                    bf[nf][0] = Bb[(8 * nf + g) * 36 + kb + q];
                    bf[nf][1] = Bb[(8 * nf + g) * 36 + kb + q + 4];
                }
#pragma unroll
                for (int mf = 0; mf < 2; mf++) {
                    int r0 = 32 * w + 16 * mf + g;
                    float a0 = Ab[r0 * 36 + kb + q];
                    float a1 = Ab[(r0 + 8) * 36 + kb + q];
                    float a2 = Ab[r0 * 36 + kb + q + 4];
                    float a3 = Ab[(r0 + 8) * 36 + kb + q + 4];
#pragma unroll
                    for (int nf = 0; nf < 4; nf++)
                        mma8(acc[mf][nf], a0, a1, a2, a3, bf[nf][0], bf[nf][1]);
                }
            }
        }
        // epilogue: gates -> cell update -> h (tf32-rounded)
#pragma unroll
        for (int mf = 0; mf < 2; mf++)
#pragma unroll
            for (int j = 0; j < 4; j++) {
                int m = 32 * w + 16 * mf + g + 8 * (j >> 1);
                int u = 2 * q + (j & 1);
                float iv = sigm(acc[mf][0][j] + bb[u]);
                float fv = sigm(acc[mf][1][j] + bb[8 + u]);
                float gv = tanhf(acc[mf][2][j] + bb[16 + u]);
                float ov = sigm(acc[mf][3][j] + bb[24 + u]);
                float cn = fv * cs[mf][j] + iv * gv;
                cs[mf][j] = cn;
                hdst[(size_t)m * Hx + cta * 8 + u] = tf32r(ov * tanhf(cn));
            }
    };

    // t=0 layer1, then per-step: sync; L2(t); L1(t+1)
    run_layer(g_h1[1], g_xp, XPAD, g_W1p, KP1, NCH1, g_bs1, c1s, g_h1[0]);
    for (int t = 0; t < Tx; t++) {
        gridsync();
        const float* h1w = g_h1[t & 1];
        const float* h2r = (t == 0) ? g_hz : g_h2all + (size_t)(t - 1) * Bx * Hx;
        float*       h2w = g_h2all + (size_t)t * Bx * Hx;
        run_layer(h1w, h2r, 1024, g_W2p, KP2, NCH2, g_bs2, c2s, h2w);
        if (t + 1 < Tx)
            run_layer(h1w, g_xp + (size_t)(t + 1) * Bx * XPAD, XPAD,
                      g_W1p, KP1, NCH1, g_bs1, c1s, g_h1[(t + 1) & 1]);
    }
}

// ---- MLP head (R6-proven mma.sync path) ----
struct SMt {
    float As[2][128 * 36];
    float Bs[2][32 * 36];
    float bb[32];
};

template <int MODE>
__device__ __forceinline__ void hgemm(const float* __restrict__ A0, long s0,
                                      const float* __restrict__ W, int KP,
                                      const float* __restrict__ bias,
                                      float* out, int cta, int row0, SMt& sm) {
    const int tid = threadIdx.x;
    const int w = tid >> 5, l = tid & 31, g = l >> 2, q = l & 3;
    const int nch = KP >> 5;
    if (tid < 32) sm.bb[tid] = bias[cta * 32 + tid];
    float acc[4][4];
#pragma unroll
    for (int a = 0; a < 4; a++)
#pragma unroll
        for (int j = 0; j < 4; j++) acc[a][j] = 0.f;

    auto stg = [&](int ch) {
        int k0 = ch << 5;
        float* Ab = sm.As[ch & 1];
        float* Bb = sm.Bs[ch & 1];
#pragma unroll
        for (int i = tid; i < 1024; i += 256) {
            int r = i >> 3, qq = i & 7;
            cp16g(Ab + r * 36 + qq * 4, A0 + (row0 + r) * s0 + k0 + qq * 4);
        }
        {
            int c = tid >> 3, qq = tid & 7;
            cp16g(Bb + c * 36 + qq * 4, W + (size_t)(cta * 32 + c) * KP + k0 + qq * 4);
        }
        asm volatile("cp.async.commit_group;");
    };

    stg(0);
    for (int ch = 0; ch < nch; ch++) {
        if (ch + 1 < nch) { stg(ch + 1); asm volatile("cp.async.wait_group 1;"); }
        else              { asm volatile("cp.async.wait_group 0;"); }
        __syncthreads();
        const float* Ab = sm.As[ch & 1];
        const float* Bb = sm.Bs[ch & 1];
#pragma unroll
        for (int kf = 0; kf < 4; kf++) {
            int kb = kf << 3;
            float a0 = tf32r(Ab[(16 * w + g) * 36 + kb + q]);
            float a1 = tf32r(Ab[(16 * w + g + 8) * 36 + kb + q]);
            float a2 = tf32r(Ab[(16 * w + g) * 36 + kb + q + 4]);
            float a3 = tf32r(Ab[(16 * w + g + 8) * 36 + kb + q + 4]);
#pragma unroll
            for (int nf = 0; nf < 4; nf++) {
                float b0 = Bb[(8 * nf + g) * 36 + kb + q];
                float b1 = Bb[(8 * nf + g) * 36 + kb + q + 4];
                mma8(acc[nf], a0, a1, a2, a3, b0, b1);
            }
        }
        __syncthreads();
    }
#pragma unroll
    for (int nf = 0; nf < 4; nf++)
#pragma unroll
        for (int j = 0; j < 4; j++) {
            int m = 16 * w + g + 8 * (j >> 1);
            int col = cta * 32 + 8 * nf + 2 * q + (j & 1);
            float v = acc[nf][j] + sm.bb[8 * nf + 2 * q + (j & 1)];
            if (MODE == 1)
                v = v > 0.f ? 1.0507009873554805f * v
                            : 1.7580993408473766f * (__expf(v) - 1.f);
            out[(size_t)(row0 + m) * 128 + col] = v;
        }
}

__global__ void __launch_bounds__(256) headk(int mode, const float* __restrict__ A,
                                             long sA, const float* __restrict__ W, int KP,
                                             const float* __restrict__ bias, float* out) {
    __shared__ SMt sm;
    if (mode == 1)
        hgemm<1>(A, sA, W, KP, bias, out, blockIdx.x, blockIdx.y * 128, sm);
    else
        hgemm<2>(A, sA, W, KP, bias, out, blockIdx.x, blockIdx.y * 128, sm);
}

extern "C" void kernel_launch(void* const* d_in, const int* in_sizes, int n_in,
                              void* d_out, int out_size) {
    const float* x    = (const float*)d_in[0];
    const float* Wih1 = (const float*)d_in[1]; const float* bih1 = (const float*)d_in[2];
    const float* Whh1 = (const float*)d_in[3]; const float* bhh1 = (const float*)d_in[4];
    const float* Wih2 = (const float*)d_in[5]; const float* bih2 = (const float*)d_in[6];
    const float* Whh2 = (const float*)d_in[7]; const float* bhh2 = (const float*)d_in[8];
    const float* W1   = (const float*)d_in[9]; const float* b1   = (const float*)d_in[10];
    const float* W2   = (const float*)d_in[11]; const float* b2  = (const float*)d_in[12];

    float *Wh1p, *Wh2p, *h2all, *hid;
    cudaGetSymbolAddress((void**)&Wh1p,  g_Wh1p);
    cudaGetSymbolAddress((void**)&Wh2p,  g_Wh2p);
    cudaGetSymbolAddress((void**)&h2all, g_h2all);
    cudaGetSymbolAddress((void**)&hid,   g_hid);

    int psm = (3 * 4608 + 3 * 1152 + 32) * 4;
    cudaFuncSetAttribute(persist, cudaFuncAttributeMaxDynamicSharedMemorySize, psm);

    initz<<<128, 256>>>();
    prepack<<<1024, 256>>>(x, Wih1, bih1, Whh1, bhh1, Wih2, bih2, Whh2, bhh2, W1, W2);
    dummyk<<<1, 32>>>();
    dummyk<<<1, 32>>>();
    dummyk<<<1, 32>>>();
    persist<<<NCTA, 128, psm>>>();
    headk<<<dim3(4, 1024), 256>>>(1, h2all, 1024, Wh1p, 1024, b1, hid);
    headk<<<dim3(4, 1024), 256>>>(2, hid, 128, Wh2p, 128, b2, (float*)d_out);
}

// round 13
// speedup vs baseline: 1.5306x; 1.4213x over previous
#include <cuda_runtime.h>
#include <cuda_fp16.h>
#include <cstdint>
#include <cstddef>

#define Bx 128
#define Hx 1024
#define Fx 138
#define Tx 1024
#define NCTA 128
#define KP1 1184
#define KP2 2048
#define XPAD 160
#define NCH1 37
#define NCH2 64
#define RSW 40   // smem row stride in halves (20 words -> conflict-free)

// ---- persistent scratch ----
__device__ __half g_W1p[4096L * KP1];
__device__ __half g_W2p[4096L * KP2];
__device__ __half g_Wh1p[128L * 1024];
__device__ __half g_Wh2p[128L * 128];
__device__ float g_bs1[4096], g_bs2[4096];
__device__ __half g_xp[(size_t)Tx * Bx * XPAD];
__device__ __half g_h1[2][Bx * Hx];
__device__ __half g_hz[Bx * Hx];
__device__ __half g_h2all[(size_t)Tx * Bx * Hx];
__device__ __half g_hid[(size_t)Tx * Bx * 128];
__device__ unsigned g_cnt, g_gen;

// ---- helpers ----
__device__ __forceinline__ float sigm(float x) { return 1.f / (1.f + __expf(-x)); }
__device__ __forceinline__ void cp16h(__half* d, const __half* s) {
    uint32_t a = (uint32_t)__cvta_generic_to_shared(d);
    asm volatile("cp.async.ca.shared.global [%0], [%1], 16;" :: "r"(a), "l"(s));
}
__device__ __forceinline__ void mma16(float* c, uint32_t a0, uint32_t a1, uint32_t a2,
                                      uint32_t a3, uint32_t b0, uint32_t b1) {
    asm volatile(
        "mma.sync.aligned.m16n8k16.row.col.f32.f16.f16.f32 "
        "{%0,%1,%2,%3},{%4,%5,%6,%7},{%8,%9},{%0,%1,%2,%3};"
        : "+f"(c[0]), "+f"(c[1]), "+f"(c[2]), "+f"(c[3])
        : "r"(a0), "r"(a1), "r"(a2), "r"(a3), "r"(b0), "r"(b1));
}

__device__ __forceinline__ void gridsync() {
    __syncthreads();
    if (threadIdx.x == 0) {
        __threadfence();
        volatile unsigned* genp = &g_gen;
        unsigned gen = *genp;
        if (atomicAdd(&g_cnt, 1u) == NCTA - 1) {
            g_cnt = 0;
            __threadfence();
            *genp = gen + 1;
        } else {
            while (*genp == gen) __nanosleep(64);
        }
        __threadfence();
    }
    __syncthreads();
}

__global__ void initz() {
    for (int i = blockIdx.x * blockDim.x + threadIdx.x; i < Bx * Hx;
         i += gridDim.x * blockDim.x) {
        g_h1[0][i] = __float2half(0.f);
        g_h1[1][i] = __float2half(0.f);
        g_hz[i] = __float2half(0.f);
    }
}

__global__ void dummyk() {}

// ---- prepack: gate-interleave (32-col CTA groups) + fp16 + x pad ----
// packed row p: cta=p>>5, gate=(p>>3)&3, u=p&7 -> r = gate*1024 + (p>>5)*8 + (p&7)
__global__ void prepack(const float* __restrict__ x,
                        const float* __restrict__ Wih1, const float* __restrict__ bih1,
                        const float* __restrict__ Whh1, const float* __restrict__ bhh1,
                        const float* __restrict__ Wih2, const float* __restrict__ bih2,
                        const float* __restrict__ Whh2, const float* __restrict__ bhh2,
                        const float* __restrict__ W1, const float* __restrict__ W2) {
    long t0 = blockIdx.x * (long)blockDim.x + threadIdx.x;
    long st = (long)gridDim.x * blockDim.x;
    for (long i = t0; i < 4096L * KP2; i += st) {
        int p = (int)(i >> 11), k = (int)(i & 2047);
        int r = ((p >> 3) & 3) * 1024 + (p >> 5) * 8 + (p & 7);
        g_W2p[i] = __float2half_rn(k < 1024 ? Wih2[(long)r * 1024 + k]
                                            : Whh2[(long)r * 1024 + k - 1024]);
    }
    for (long i = t0; i < 4096L * KP1; i += st) {
        int p = (int)(i / KP1), k = (int)(i % KP1);
        int r = ((p >> 3) & 3) * 1024 + (p >> 5) * 8 + (p & 7);
        float v = 0.f;
        if (k < 1024) v = Whh1[(long)r * 1024 + k];
        else if (k < 1024 + Fx) v = Wih1[(long)r * Fx + k - 1024];
        g_W1p[i] = __float2half_rn(v);
    }
    for (long i = t0; i < (long)Tx * Bx * XPAD; i += st) {
        long rb = i / XPAD; int k = (int)(i % XPAD);
        g_xp[i] = __float2half_rn((k < Fx) ? x[rb * Fx + k] : 0.f);
    }
    for (long i = t0; i < 128L * 1024; i += st) g_Wh1p[i] = __float2half_rn(W1[i]);
    for (long i = t0; i < 128L * 128;  i += st) g_Wh2p[i] = __float2half_rn(W2[i]);
    for (long i = t0; i < 4096; i += st) {
        int p = (int)i;
        int r = ((p >> 3) & 3) * 1024 + (p >> 5) * 8 + (p & 7);
        g_bs1[p] = bih1[r] + bhh1[r];
        g_bs2[p] = bih2[r] + bhh2[r];
    }
}

// ---- persistent recurrence: 128 CTAs x 128 thr, fp16 m16n8k16, warp tile M32xN32 ----
__global__ void __launch_bounds__(128, 1) persist() {
    extern __shared__ __half hsm[];
    __half* As = hsm;                        // [3][128*RSW]
    __half* Bs = hsm + 3 * 128 * RSW;        // [3][32*RSW]
    float*  bb = (float*)(hsm + 3 * 128 * RSW + 3 * 32 * RSW);  // [32]
    const int tid = threadIdx.x, cta = blockIdx.x;
    const int w = tid >> 5, l = tid & 31, g = l >> 2, q = l & 3;

    float c1s[2][4], c2s[2][4];
#pragma unroll
    for (int a = 0; a < 2; a++)
#pragma unroll
        for (int j = 0; j < 4; j++) { c1s[a][j] = 0.f; c2s[a][j] = 0.f; }

    auto run_layer = [&](const __half* __restrict__ A0, const __half* __restrict__ A1,
                         long s1, const __half* __restrict__ W, int KP, int nch,
                         const float* __restrict__ bias, float (*cs)[4],
                         __half* __restrict__ hdst) {
        __syncthreads();   // protect bb + smem bufs vs previous layer's readers
        if (tid < 32) bb[tid] = bias[cta * 32 + tid];

        float acc[2][4][4];
#pragma unroll
        for (int mf = 0; mf < 2; mf++)
#pragma unroll
            for (int nf = 0; nf < 4; nf++)
#pragma unroll
                for (int j = 0; j < 4; j++) acc[mf][nf][j] = 0.f;

        auto stage = [&](int c) {
            int jb = c % 3, k0 = c << 5;
            __half* Ab = As + jb * 128 * RSW;
            __half* Bb = Bs + jb * 32 * RSW;
            const bool inA0 = (k0 < 1024);
#pragma unroll
            for (int it = 0; it < 4; it++) {
                int i = tid + it * 128;
                int r = i >> 2, q8 = i & 3;       // r: 0..127, q8: 0..3 (8 halves each)
                const __half* src = inA0 ? A0 + (size_t)r * 1024 + k0 + q8 * 8
                                         : A1 + (size_t)r * s1 + (k0 - 1024) + q8 * 8;
                cp16h(Ab + r * RSW + q8 * 8, src);
            }
            {
                int n = tid >> 2, q8 = tid & 3;   // 128 thr cover 32 rows x 4
                cp16h(Bb + n * RSW + q8 * 8,
                      W + (size_t)(cta * 32 + n) * KP + k0 + q8 * 8);
            }
            asm volatile("cp.async.commit_group;" ::: "memory");
        };

        stage(0); stage(1);
        for (int c = 0; c < nch; c++) {
            if (c + 1 < nch) asm volatile("cp.async.wait_group 1;" ::: "memory");
            else             asm volatile("cp.async.wait_group 0;" ::: "memory");
            __syncthreads();
            if (c + 2 < nch) stage(c + 2);
            const uint32_t* Aw = (const uint32_t*)(As + (c % 3) * 128 * RSW);  // 20 words/row
            const uint32_t* Bw = (const uint32_t*)(Bs + (c % 3) * 32 * RSW);
#pragma unroll
            for (int kb = 0; kb < 2; kb++) {       // two k16 blocks in K32 chunk
                int ko = kb * 8;                   // word offset
                uint32_t bf[4][2];
#pragma unroll
                for (int nf = 0; nf < 4; nf++) {
                    bf[nf][0] = Bw[(8 * nf + g) * 20 + ko + q];
                    bf[nf][1] = Bw[(8 * nf + g) * 20 + ko + q + 4];
                }
#pragma unroll
                for (int mf = 0; mf < 2; mf++) {
                    int r0 = 32 * w + 16 * mf;
                    uint32_t a0 = Aw[(r0 + g) * 20 + ko + q];
                    uint32_t a1 = Aw[(r0 + g + 8) * 20 + ko + q];
                    uint32_t a2 = Aw[(r0 + g) * 20 + ko + q + 4];
                    uint32_t a3 = Aw[(r0 + g + 8) * 20 + ko + q + 4];
#pragma unroll
                    for (int nf = 0; nf < 4; nf++)
                        mma16(acc[mf][nf], a0, a1, a2, a3, bf[nf][0], bf[nf][1]);
                }
            }
        }
        // epilogue: gates -> cell update -> h (fp16 store)
#pragma unroll
        for (int mf = 0; mf < 2; mf++)
#pragma unroll
            for (int j = 0; j < 4; j++) {
                int m = 32 * w + 16 * mf + g + 8 * (j >> 1);
                int u = 2 * q + (j & 1);
                float iv = sigm(acc[mf][0][j] + bb[u]);
                float fv = sigm(acc[mf][1][j] + bb[8 + u]);
                float gv = tanhf(acc[mf][2][j] + bb[16 + u]);
                float ov = sigm(acc[mf][3][j] + bb[24 + u]);
                float cn = fv * cs[mf][j] + iv * gv;
                cs[mf][j] = cn;
                hdst[(size_t)m * Hx + cta * 8 + u] = __float2half_rn(ov * tanhf(cn));
            }
    };

    // t=0 layer1, then per-step: sync; L2(t); L1(t+1)
    run_layer(g_h1[1], g_xp, XPAD, g_W1p, KP1, NCH1, g_bs1, c1s, g_h1[0]);
    for (int t = 0; t < Tx; t++) {
        gridsync();
        const __half* h1w = g_h1[t & 1];
        const __half* h2r = (t == 0) ? g_hz : g_h2all + (size_t)(t - 1) * Bx * Hx;
        __half*       h2w = g_h2all + (size_t)t * Bx * Hx;
        run_layer(h1w, h2r, 1024, g_W2p, KP2, NCH2, g_bs2, c2s, h2w);
        if (t + 1 < Tx)
            run_layer(h1w, g_xp + (size_t)(t + 1) * Bx * XPAD, XPAD,
                      g_W1p, KP1, NCH1, g_bs1, c1s, g_h1[(t + 1) & 1]);
    }
}

// ---- MLP head: fp16 m16n8k16, 256 thr, warp tile M16xN32 ----
struct SMh {
    __half As[2][128 * RSW];
    __half Bs[2][32 * RSW];
    float bb[32];
};

// MODE 1: selu -> half out (stride 128); MODE 2: plain -> float out (stride 128)
template <int MODE, typename OUT>
__device__ __forceinline__ void hgemm(const __half* __restrict__ A0, long s0,
                                      const __half* __restrict__ W, int KP,
                                      const float* __restrict__ bias,
                                      OUT* out, int cta, int row0, SMh& sm) {
    const int tid = threadIdx.x;
    const int w = tid >> 5, l = tid & 31, g = l >> 2, q = l & 3;
    const int nch = KP >> 5;
    if (tid < 32) sm.bb[tid] = bias[cta * 32 + tid];
    float acc[4][4];
#pragma unroll
    for (int a = 0; a < 4; a++)
#pragma unroll
        for (int j = 0; j < 4; j++) acc[a][j] = 0.f;

    auto stg = [&](int ch) {
        int k0 = ch << 5;
        __half* Ab = sm.As[ch & 1];
        __half* Bb = sm.Bs[ch & 1];
#pragma unroll
        for (int it = 0; it < 2; it++) {
            int i = tid + it * 256;
            int r = i >> 2, q8 = i & 3;
            cp16h(Ab + r * RSW + q8 * 8, A0 + (size_t)(row0 + r) * s0 + k0 + q8 * 8);
        }
        if (tid < 128) {
            int n = tid >> 2, q8 = tid & 3;
            cp16h(Bb + n * RSW + q8 * 8, W + (size_t)(cta * 32 + n) * KP + k0 + q8 * 8);
        }
        asm volatile("cp.async.commit_group;");
    };

    stg(0);
    for (int ch = 0; ch < nch; ch++) {
        if (ch + 1 < nch) { stg(ch + 1); asm volatile("cp.async.wait_group 1;"); }
        else              { asm volatile("cp.async.wait_group 0;"); }
        __syncthreads();
        const uint32_t* Aw = (const uint32_t*)sm.As[ch & 1];
        const uint32_t* Bw = (const uint32_t*)sm.Bs[ch & 1];
#pragma unroll
        for (int kb = 0; kb < 2; kb++) {
            int ko = kb * 8;
            uint32_t a0 = Aw[(16 * w + g) * 20 + ko + q];
            uint32_t a1 = Aw[(16 * w + g + 8) * 20 + ko + q];
            uint32_t a2 = Aw[(16 * w + g) * 20 + ko + q + 4];
            uint32_t a3 = Aw[(16 * w + g + 8) * 20 + ko + q + 4];
#pragma unroll
            for (int nf = 0; nf < 4; nf++) {
                uint32_t b0 = Bw[(8 * nf + g) * 20 + ko + q];
                uint32_t b1 = Bw[(8 * nf + g) * 20 + ko + q + 4];
                mma16(acc[nf], a0, a1, a2, a3, b0, b1);
            }
        }
        __syncthreads();
    }
#pragma unroll
    for (int nf = 0; nf < 4; nf++)
#pragma unroll
        for (int j = 0; j < 4; j++) {
            int m = 16 * w + g + 8 * (j >> 1);
            int col = cta * 32 + 8 * nf + 2 * q + (j & 1);
            float v = acc[nf][j] + sm.bb[8 * nf + 2 * q + (j & 1)];
            if (MODE == 1) {
                v = v > 0.f ? 1.0507009873554805f * v
                            : 1.7580993408473766f * (__expf(v) - 1.f);
                ((__half*)out)[(size_t)(row0 + m) * 128 + col] = __float2half_rn(v);
            } else {
                ((float*)out)[(size_t)(row0 + m) * 128 + col] = v;
            }
        }
}

__global__ void __launch_bounds__(256) headk1(const __half* __restrict__ A, long sA,
                                              const __half* __restrict__ W, int KP,
                                              const float* __restrict__ bias, __half* out) {
    __shared__ SMh sm;
    hgemm<1, __half>(A, sA, W, KP, bias, out, blockIdx.x, blockIdx.y * 128, sm);
}
__global__ void __launch_bounds__(256) headk2(const __half* __restrict__ A, long sA,
                                              const __half* __restrict__ W, int KP,
                                              const float* __restrict__ bias, float* out) {
    __shared__ SMh sm;
    hgemm<2, float>(A, sA, W, KP, bias, out, blockIdx.x, blockIdx.y * 128, sm);
}

extern "C" void kernel_launch(void* const* d_in, const int* in_sizes, int n_in,
                              void* d_out, int out_size) {
    const float* x    = (const float*)d_in[0];
    const float* Wih1 = (const float*)d_in[1]; const float* bih1 = (const float*)d_in[2];
    const float* Whh1 = (const float*)d_in[3]; const float* bhh1 = (const float*)d_in[4];
    const float* Wih2 = (const float*)d_in[5]; const float* bih2 = (const float*)d_in[6];
    const float* Whh2 = (const float*)d_in[7]; const float* bhh2 = (const float*)d_in[8];
    const float* W1   = (const float*)d_in[9]; const float* b1   = (const float*)d_in[10];
    const float* W2   = (const float*)d_in[11]; const float* b2  = (const float*)d_in[12];

    __half *Wh1p, *Wh2p, *h2all, *hid;
    cudaGetSymbolAddress((void**)&Wh1p,  g_Wh1p);
    cudaGetSymbolAddress((void**)&Wh2p,  g_Wh2p);
    cudaGetSymbolAddress((void**)&h2all, g_h2all);
    cudaGetSymbolAddress((void**)&hid,   g_hid);

    int psm = (3 * 128 * RSW + 3 * 32 * RSW) * 2 + 32 * 4;
    cudaFuncSetAttribute(persist, cudaFuncAttributeMaxDynamicSharedMemorySize, psm);

    initz<<<128, 256>>>();
    prepack<<<1024, 256>>>(x, Wih1, bih1, Whh1, bhh1, Wih2, bih2, Whh2, bhh2, W1, W2);
    dummyk<<<1, 32>>>();
    dummyk<<<1, 32>>>();
    persist<<<NCTA, 128, psm>>>();
    headk1<<<dim3(4, 1024), 256>>>(h2all, 1024, Wh1p, 1024, b1, hid);
    headk2<<<dim3(4, 1024), 256>>>(hid, 128, Wh2p, 128, b2, (float*)d_out);
}